// round 2
// baseline (speedup 1.0000x reference)
#include <cuda_runtime.h>
#include <cuda_bf16.h>
#include <cstdint>

// ============================================================================
// CellLSTM on GB300 (sm_103a)
//   z = [x|h] @ [Wi|Wf|Wg|Wo] + b ; gates; c' = f*c + i*g ; h' = o*tanh(c')
//   GEMM M=8192, K=2048, N=4096 via tcgen05 bf16x3 split (fp32-accurate).
//   tcgen05 is an arch-SPECIFIC ("a") feature: compiled only when the pass
//   defines __CUDA_ARCH_FEAT_SM103_ALL / SM100_ALL. Plain compute_103 passes
//   get a correct SIMT fallback so ptxas never sees tcgen05 on .target sm_103.
// ============================================================================

#if defined(__CUDA_ARCH_FEAT_SM103_ALL) || defined(__CUDA_ARCH_FEAT_SM100_ALL)
#define USE_TCGEN05 1
#else
#define USE_TCGEN05 0
#endif

#define B_DIM 8192
#define T_DIM 1024
#define U_DIM 1024
#define K_DIM 2048
#define N_DIM 4096

#define BM 128
#define BN 128
#define BK 64
#define KTILES (K_DIM / BK)   // 32
#define GEMM_THREADS 256

// ---------------- scratch (device globals: allocation-rule-safe) -----------
__device__ __align__(16) __nv_bfloat16 g_A_hi[(size_t)B_DIM * K_DIM];
__device__ __align__(16) __nv_bfloat16 g_A_lo[(size_t)B_DIM * K_DIM];
// W transposed & gate-interleaved: row n = u*4 + gate, K-major
__device__ __align__(16) __nv_bfloat16 g_W_hi[(size_t)N_DIM * K_DIM];
__device__ __align__(16) __nv_bfloat16 g_W_lo[(size_t)N_DIM * K_DIM];

// ---------------- PTX helpers (arch-neutral ones) ---------------------------
__device__ __forceinline__ uint32_t smem_u32(const void* p) {
    uint32_t a;
    asm("{ .reg .u64 t; cvta.to.shared.u64 t, %1; cvt.u32.u64 %0, t; }"
        : "=r"(a) : "l"(p));
    return a;
}

#define SWZ128(off) ((off) ^ (((off) >> 3) & 0x70))

#if USE_TCGEN05
// ---------------- tcgen05 / mbarrier / cp.async helpers --------------------
__device__ __forceinline__ uint32_t elect_one() {
    uint32_t pred;
    asm volatile(
        "{\n\t.reg .pred p;\n\telect.sync _|p, 0xFFFFFFFF;\n\t"
        "selp.b32 %0, 1, 0, p;\n\t}" : "=r"(pred));
    return pred;
}

#define MBARRIER_INIT(addr, cnt) \
    asm volatile("mbarrier.init.shared.b64 [%0], %1;" \
                 :: "r"((uint32_t)(addr)), "r"((uint32_t)(cnt)) : "memory")

#define MBARRIER_INVAL(addr) \
    asm volatile("mbarrier.inval.shared.b64 [%0];" \
                 :: "r"((uint32_t)(addr)) : "memory")

#define MBARRIER_WAIT_PARITY(mbar_smem_addr, phase_parity) do { \
    uint32_t _mbar = (uint32_t)(mbar_smem_addr); \
    uint32_t _parity = (uint32_t)(phase_parity); \
    uint32_t _done; \
    asm volatile( \
        "{\n\t.reg .pred p;\n\t" \
        "mbarrier.try_wait.parity.acquire.cta.shared::cta.b64 p, [%1], %2;\n\t" \
        "selp.b32 %0, 1, 0, p;\n\t}" \
        : "=r"(_done) : "r"(_mbar), "r"(_parity) : "memory"); \
    if (!_done) { \
        asm volatile( \
            "{\n\t.reg .pred P1;\n\t" \
            "WAIT_LOOP_%=:\n\t" \
            "mbarrier.try_wait.parity.acquire.cta.shared::cta.b64 P1, [%0], %1, 0x989680;\n\t" \
            "@P1 bra.uni WAIT_DONE_%=;\n\t" \
            "bra.uni WAIT_LOOP_%=;\n\t" \
            "WAIT_DONE_%=:\n\t}" \
            :: "r"(_mbar), "r"(_parity) : "memory"); \
    } \
} while (0)

#define TCGEN05_ALLOC(smem_result_addr, nCols) \
    asm volatile("tcgen05.alloc.cta_group::1.sync.aligned.shared::cta.b32 [%0], %1;" \
                 :: "r"((uint32_t)(smem_result_addr)), "r"((uint32_t)(nCols)) : "memory")

#define TCGEN05_DEALLOC(tmem_addr, nCols) \
    asm volatile("tcgen05.dealloc.cta_group::1.sync.aligned.b32 %0, %1;" \
                 :: "r"(tmem_addr), "r"((uint32_t)(nCols)))

#define TCGEN05_COMMIT(mbar_smem_addr) \
    asm volatile("tcgen05.commit.cta_group::1.mbarrier::arrive::one.shared::cluster.b64 [%0];" \
                 :: "r"((uint32_t)(mbar_smem_addr)) : "memory")

#define TCGEN05_FENCE_AFTER() \
    asm volatile("tcgen05.fence::after_thread_sync;" ::: "memory")
#define TCGEN05_FENCE_BEFORE() \
    asm volatile("tcgen05.fence::before_thread_sync;" ::: "memory")
#define TCGEN05_WAIT_LD() \
    asm volatile("tcgen05.wait::ld.sync.aligned;" ::: "memory")

#define FENCE_PROXY_ASYNC() \
    asm volatile("fence.proxy.async.shared::cta;" ::: "memory")

#define CP_ASYNC_COMMIT() asm volatile("cp.async.commit_group;" ::: "memory")
#define CP_ASYNC_WAIT(n)  asm volatile("cp.async.wait_group %0;" :: "n"(n) : "memory")

__device__ __forceinline__ void cp16(uint32_t dst, const void* src) {
    asm volatile("cp.async.cg.shared.global [%0], [%1], 16;"
                 :: "r"(dst), "l"(src) : "memory");
}

#define TCGEN05_LD_32X32B_X32(r, tmem_addr) \
    asm volatile( \
        "tcgen05.ld.sync.aligned.32x32b.x32.b32 " \
        "{%0, %1, %2, %3, %4, %5, %6, %7, " \
        " %8, %9, %10, %11, %12, %13, %14, %15, " \
        " %16, %17, %18, %19, %20, %21, %22, %23, " \
        " %24, %25, %26, %27, %28, %29, %30, %31}, [%32];" \
        : "=r"((r)[0]),  "=r"((r)[1]),  "=r"((r)[2]),  "=r"((r)[3]), \
          "=r"((r)[4]),  "=r"((r)[5]),  "=r"((r)[6]),  "=r"((r)[7]), \
          "=r"((r)[8]),  "=r"((r)[9]),  "=r"((r)[10]), "=r"((r)[11]), \
          "=r"((r)[12]), "=r"((r)[13]), "=r"((r)[14]), "=r"((r)[15]), \
          "=r"((r)[16]), "=r"((r)[17]), "=r"((r)[18]), "=r"((r)[19]), \
          "=r"((r)[20]), "=r"((r)[21]), "=r"((r)[22]), "=r"((r)[23]), \
          "=r"((r)[24]), "=r"((r)[25]), "=r"((r)[26]), "=r"((r)[27]), \
          "=r"((r)[28]), "=r"((r)[29]), "=r"((r)[30]), "=r"((r)[31]) \
        : "r"(tmem_addr))

// K-major SW128 smem descriptor (verified pattern: test_mma_iter / 2cta_bf16)
static constexpr uint64_t SMEM_DESC_BASE_SW128 =
    (uint64_t(2)  << 61) | (uint64_t(1) << 46) |
    (uint64_t(64) << 32) | (uint64_t(1) << 16);

__device__ __forceinline__ uint64_t make_desc(uint32_t addr) {
    return SMEM_DESC_BASE_SW128 | ((uint64_t)(addr >> 4) & 0x3FFF);
}

// idesc for kind::f16 (bf16/bf16 -> f32), M=128, N=128  -> 0x8200490
static constexpr uint32_t MMA_IDESC =
    (1u << 4) | (1u << 7) | (1u << 10) | ((BN / 8) << 17) | ((BM / 16) << 24);

__device__ __forceinline__ void mma_f16_ss(uint32_t d, uint64_t ad, uint64_t bd,
                                           uint32_t idesc, uint32_t acc) {
    asm volatile(
        "{\n\t.reg .pred p;\n\t"
        "setp.ne.u32 p, %4, 0;\n\t"
        "tcgen05.mma.cta_group::1.kind::f16 [%0], %1, %2, %3, {%5, %5, %5, %5}, p;\n\t"
        "}"
        :: "r"(d), "l"(ad), "l"(bd), "r"(idesc), "r"(acc), "r"(0u)
        : "memory");
}
#endif // USE_TCGEN05

// ---------------- prep kernel A: concat(x,h) -> bf16 hi/lo -----------------
__global__ void prep_a_kernel(const float* __restrict__ x, const float* __restrict__ h) {
    size_t idx4 = ((size_t)blockIdx.x * blockDim.x + threadIdx.x) * 4;
    int m = (int)(idx4 / K_DIM);
    int k = (int)(idx4 % K_DIM);
    const float* src = (k < T_DIM) ? (x + (size_t)m * T_DIM + k)
                                   : (h + (size_t)m * U_DIM + (k - T_DIM));
    float4 v = *reinterpret_cast<const float4*>(src);

    __nv_bfloat16 h0 = __float2bfloat16(v.x);
    __nv_bfloat16 h1 = __float2bfloat16(v.y);
    __nv_bfloat16 h2 = __float2bfloat16(v.z);
    __nv_bfloat16 h3 = __float2bfloat16(v.w);
    __nv_bfloat16 l0 = __float2bfloat16(v.x - __bfloat162float(h0));
    __nv_bfloat16 l1 = __float2bfloat16(v.y - __bfloat162float(h1));
    __nv_bfloat16 l2 = __float2bfloat16(v.z - __bfloat162float(h2));
    __nv_bfloat16 l3 = __float2bfloat16(v.w - __bfloat162float(h3));

    union Pack { __nv_bfloat16 b[4]; uint2 u; } ph, pl;
    ph.b[0] = h0; ph.b[1] = h1; ph.b[2] = h2; ph.b[3] = h3;
    pl.b[0] = l0; pl.b[1] = l1; pl.b[2] = l2; pl.b[3] = l3;
    *reinterpret_cast<uint2*>(g_A_hi + idx4) = ph.u;
    *reinterpret_cast<uint2*>(g_A_lo + idx4) = pl.u;
}

// ---------------- prep kernel B: W transpose+convert, gate-interleaved -----
__global__ void prep_w_kernel(const float* __restrict__ Wi, const float* __restrict__ Wf,
                              const float* __restrict__ Wg, const float* __restrict__ Wo) {
    __shared__ float tile[32][33];
    int gate = blockIdx.z;
    const float* W = (gate == 0) ? Wi : (gate == 1) ? Wf : (gate == 2) ? Wg : Wo;
    int k0 = blockIdx.x * 32;
    int u0 = blockIdx.y * 32;
    int tx = threadIdx.x, ty = threadIdx.y;

#pragma unroll
    for (int i = 0; i < 4; i++) {
        int k = k0 + ty + i * 8;
        tile[ty + i * 8][tx] = W[(size_t)k * U_DIM + u0 + tx];  // coalesced over u
    }
    __syncthreads();
#pragma unroll
    for (int i = 0; i < 4; i++) {
        int u = u0 + ty + i * 8;
        float v = tile[tx][ty + i * 8];          // = W[k0+tx, u]
        __nv_bfloat16 hi = __float2bfloat16(v);
        __nv_bfloat16 lo = __float2bfloat16(v - __bfloat162float(hi));
        size_t off = (size_t)(u * 4 + gate) * K_DIM + k0 + tx;  // coalesced over k
        g_W_hi[off] = hi;
        g_W_lo[off] = lo;
    }
}

// ---------------- GEMM + LSTM epilogue -------------------------------------
// smem (tcgen05 path): [0] tmem ptr, [8] mbar,
//   [1024..] 2 stages x (A_hi, A_lo, W_hi, W_lo) 16KB each
#define SM_TMEM 0
#define SM_MBAR 8
#define SM_TILES 1024
#define STAGE_BYTES (4 * BM * BK * 2)     // 65536
#define GEMM_SMEM (SM_TILES + 2 * STAGE_BYTES)

#if USE_TCGEN05
__device__ __forceinline__ void load_stage(uint32_t sbase, int kt, int m0, int n0, int tid) {
    int koff = kt * BK;
#pragma unroll
    for (int j = 0; j < 4; j++) {
        int chunk = tid + j * GEMM_THREADS;   // 0..1023
        int r = chunk >> 3;                   // row 0..127
        int c = chunk & 7;                    // 16B chunk in 128B row
        uint32_t soff = SWZ128((uint32_t)(r * 128 + c * 16));
        size_t ga = (size_t)(m0 + r) * K_DIM + koff + c * 8;
        size_t gb = (size_t)(n0 + r) * K_DIM + koff + c * 8;
        cp16(sbase + 0 * 16384 + soff, g_A_hi + ga);
        cp16(sbase + 1 * 16384 + soff, g_A_lo + ga);
        cp16(sbase + 2 * 16384 + soff, g_W_hi + gb);
        cp16(sbase + 3 * 16384 + soff, g_W_lo + gb);
    }
}
#endif

__device__ __forceinline__ float fast_sigmoid(float z) {
    return 1.0f / (1.0f + __expf(-z));
}

__global__ void __launch_bounds__(GEMM_THREADS, 1)
lstm_gemm_kernel(const float* __restrict__ c_in,
                 const float* __restrict__ bi, const float* __restrict__ bf_,
                 const float* __restrict__ bg, const float* __restrict__ bo,
                 float* __restrict__ out) {
    extern __shared__ char smem[];
    int tid = threadIdx.x;

    int n0 = blockIdx.x * BN;   // 32 tiles
    int m0 = blockIdx.y * BM;   // 64 tiles
    int u0 = n0 >> 2;           // 32 u's per tile (4 gates interleaved)
    const size_t c_off = (size_t)B_DIM * U_DIM;

#if USE_TCGEN05
    // ======================= tcgen05 path ===================================
    uint32_t sb = smem_u32(smem);
    int wid = tid >> 5;
    int lid = tid & 31;

    if (wid == 0) TCGEN05_ALLOC(sb + SM_TMEM, 128);
    if (tid == 0) MBARRIER_INIT(sb + SM_MBAR, 1);
    __syncthreads();
    uint32_t tmem;
    asm volatile("ld.shared.b32 %0, [%1];" : "=r"(tmem) : "r"(sb + SM_TMEM));

    load_stage(sb + SM_TILES, 0, m0, n0, tid);
    CP_ASYNC_COMMIT();

    int phase = 0;
#pragma unroll 1
    for (int kt = 0; kt < KTILES; kt++) {
        if (kt > 0) { MBARRIER_WAIT_PARITY(sb + SM_MBAR, phase); phase ^= 1; }

        if (kt + 1 < KTILES) {
            load_stage(sb + SM_TILES + ((kt + 1) & 1) * STAGE_BYTES, kt + 1, m0, n0, tid);
            CP_ASYNC_COMMIT();
            CP_ASYNC_WAIT(1);   // stage kt data landed
        } else {
            CP_ASYNC_WAIT(0);
        }
        __syncthreads();

        if (wid == 0) {
            FENCE_PROXY_ASYNC();
            uint32_t st = sb + SM_TILES + (kt & 1) * STAGE_BYTES;
            uint64_t dAh = make_desc(st);
            uint64_t dAl = make_desc(st + 16384);
            uint64_t dBh = make_desc(st + 32768);
            uint64_t dBl = make_desc(st + 49152);
            if (elect_one()) {
#pragma unroll
                for (int s = 0; s < 4; s++) {   // 4 x K=16 steps per 64-wide tile
                    uint32_t off = s * 2;       // 32B = 2 x 16B units
                    mma_f16_ss(tmem, dAh + off, dBh + off, MMA_IDESC, (kt | s) != 0);
                    mma_f16_ss(tmem, dAh + off, dBl + off, MMA_IDESC, 1u);
                    mma_f16_ss(tmem, dAl + off, dBh + off, MMA_IDESC, 1u);
                }
                TCGEN05_COMMIT(sb + SM_MBAR);
            }
        }
    }

    MBARRIER_WAIT_PARITY(sb + SM_MBAR, phase);
    TCGEN05_FENCE_AFTER();

    // epilogue: D[128 rows, 128 cols] fp32 in TMEM.
    // warps 0-3 cols 0-63, warps 4-7 cols 64-127; subpartition = wid&3.
    int sub = wid & 3;
    int half = wid >> 2;
    int m = m0 + sub * 32 + lid;
    uint32_t colbase = tmem + half * 64;

    uint32_t d[64];
    TCGEN05_LD_32X32B_X32(d, colbase);
    TCGEN05_LD_32X32B_X32(d + 32, colbase + 32);
    TCGEN05_WAIT_LD();
    TCGEN05_FENCE_BEFORE();

#pragma unroll
    for (int j = 0; j < 16; j++) {
        int u = u0 + half * 16 + j;
        float zi = __uint_as_float(d[4 * j + 0]) + bi[u];
        float zf = __uint_as_float(d[4 * j + 1]) + bf_[u];
        float zg = __uint_as_float(d[4 * j + 2]) + bg[u];
        float zo = __uint_as_float(d[4 * j + 3]) + bo[u];
        float ig = fast_sigmoid(zi);
        float fg = fast_sigmoid(zf);
        float gg = tanhf(zg);
        float og = fast_sigmoid(zo);
        float cv = c_in[(size_t)m * U_DIM + u];
        float cn = fg * cv + ig * gg;
        float hn = og * tanhf(cn);
        out[(size_t)m * U_DIM + u] = hn;          // h_new
        out[c_off + (size_t)m * U_DIM + u] = cn;  // c_new
    }

    __syncthreads();
    if (tid == 0) MBARRIER_INVAL(sb + SM_MBAR);
    if (wid == 0) TCGEN05_DEALLOC(tmem, 128);

#else
    // ======================= SIMT fallback (plain sm_103 target) ===========
    // A/W reconstructed as fp32 = hi + lo from the prepped bf16x2 scratch.
    const int PAD = 132;                       // float4-aligned row stride
    float* As = reinterpret_cast<float*>(smem);          // [32][PAD]
    float* Bs = As + 32 * PAD;                           // [32][PAD]

    int tx = tid & 15;          // n micro-tile
    int ty = tid >> 4;          // m micro-tile
    float acc[8][8];
#pragma unroll
    for (int i = 0; i < 8; i++)
#pragma unroll
        for (int j = 0; j < 8; j++) acc[i][j] = 0.0f;

#pragma unroll 1
    for (int kt = 0; kt < K_DIM / 32; kt++) {
        int koff = kt * 32;
        // load 128x32 A and W tiles (fp32 reconstructed), transposed to [k][mn]
#pragma unroll
        for (int i = 0; i < 16; i++) {
            int idx = tid + i * 256;            // 0..4095
            int kk = idx & 31;
            int r = idx >> 5;                   // 0..127
            size_t ga = (size_t)(m0 + r) * K_DIM + koff + kk;
            size_t gb = (size_t)(n0 + r) * K_DIM + koff + kk;
            As[kk * PAD + r] = __bfloat162float(g_A_hi[ga]) + __bfloat162float(g_A_lo[ga]);
            Bs[kk * PAD + r] = __bfloat162float(g_W_hi[gb]) + __bfloat162float(g_W_lo[gb]);
        }
        __syncthreads();

#pragma unroll 1
        for (int kk = 0; kk < 32; kk++) {
            float a[8], b[8];
#pragma unroll
            for (int i = 0; i < 8; i++) a[i] = As[kk * PAD + ty * 8 + i];
#pragma unroll
            for (int j = 0; j < 8; j++) b[j] = Bs[kk * PAD + tx * 8 + j];
#pragma unroll
            for (int i = 0; i < 8; i++)
#pragma unroll
                for (int j = 0; j < 8; j++) acc[i][j] += a[i] * b[j];
        }
        __syncthreads();
    }

    // epilogue: thread owns rows m0+ty*8.. (8), cols n0+tx*8.. (8 = 2 full u's)
#pragma unroll
    for (int i = 0; i < 8; i++) {
        int m = m0 + ty * 8 + i;
#pragma unroll
        for (int jj = 0; jj < 2; jj++) {
            int u = u0 + tx * 2 + jj;
            float zi = acc[i][jj * 4 + 0] + bi[u];
            float zf = acc[i][jj * 4 + 1] + bf_[u];
            float zg = acc[i][jj * 4 + 2] + bg[u];
            float zo = acc[i][jj * 4 + 3] + bo[u];
            float ig = fast_sigmoid(zi);
            float fg = fast_sigmoid(zf);
            float gg = tanhf(zg);
            float og = fast_sigmoid(zo);
            float cv = c_in[(size_t)m * U_DIM + u];
            float cn = fg * cv + ig * gg;
            float hn = og * tanhf(cn);
            out[(size_t)m * U_DIM + u] = hn;
            out[c_off + (size_t)m * U_DIM + u] = cn;
        }
    }
#endif
}

// ---------------- launch ----------------------------------------------------
extern "C" void kernel_launch(void* const* d_in, const int* in_sizes, int n_in,
                              void* d_out, int out_size) {
    const float* x  = (const float*)d_in[0];
    const float* h  = (const float*)d_in[1];
    const float* c  = (const float*)d_in[2];
    const float* Wi = (const float*)d_in[3];
    const float* Wf = (const float*)d_in[4];
    const float* Wg = (const float*)d_in[5];
    const float* Wo = (const float*)d_in[6];
    const float* bi = (const float*)d_in[7];
    const float* bf = (const float*)d_in[8];
    const float* bg = (const float*)d_in[9];
    const float* bo = (const float*)d_in[10];
    float* out = (float*)d_out;

    // 1) concat+split A
    prep_a_kernel<<<(int)(((size_t)B_DIM * K_DIM / 4) / 256), 256>>>(x, h);
    // 2) transpose+split W (gate-interleaved columns)
    prep_w_kernel<<<dim3(K_DIM / 32, U_DIM / 32, 4), dim3(32, 8)>>>(Wi, Wf, Wg, Wo);
    // 3) GEMM + LSTM epilogue (tcgen05 if the sm_103a pass exists, else SIMT)
    cudaFuncSetAttribute(lstm_gemm_kernel,
                         cudaFuncAttributeMaxDynamicSharedMemorySize, GEMM_SMEM);
    lstm_gemm_kernel<<<dim3(N_DIM / BN, B_DIM / BM), GEMM_THREADS, GEMM_SMEM>>>(
        c, bi, bf, bg, bo, out);
}